// round 9
// baseline (speedup 1.0000x reference)
#include <cuda_runtime.h>
#include <cstdint>
#include <cstddef>

#define B_  32
#define T_  2048
#define D_  512
#define L_  512
#define GW  1536          // w_w column count

#define NCTA 128
#define NTHR 256

// Per-CTA publication counters, 32B stride (one L2 sector each). No atomics.
__device__ unsigned int g_flags[NCTA * 8];
// Double-buffered h broadcast: g_hbuf[parity][l*32 + b]
__device__ float g_hbuf[2 * L_ * B_];

__device__ __forceinline__ unsigned ld_acq(const unsigned* p) {
    unsigned v;
    asm volatile("ld.acquire.gpu.global.u32 %0, [%1];" : "=r"(v) : "l"(p));
    return v;
}
__device__ __forceinline__ void st_rel(unsigned* p, unsigned v) {
    asm volatile("st.release.gpu.global.u32 [%0], %1;" :: "l"(p), "r"(v));
}

__global__ void init_kernel() {
    int tid = threadIdx.x;
    #pragma unroll
    for (int r = 0; r < 4; r++) g_flags[r * 256 + tid] = 0u;
}

// ---------------------------------------------------------------------------
// Fused persistent LSTM: per step, each CTA computes BOTH the x-part
// (x_t @ Wx, no recurrent dep — overlaps the producer wait) and the h-part
// (h_t @ Wh) for its 4 l-columns (16 gate cols), K=512 each, accumulated in
// the same registers. No precompute pass, no g_pre scratch.
//
// 128 CTAs, CTA i owns l in [4i, 4i+4). 8 warps = 8-way K split (64 k each).
// h(t) published per-CTA to double-buffered g_hbuf + per-CTA flag; each warp
// polls only its 16 producer flags. 1 CTA/SM, 212 KB smem.
// ---------------------------------------------------------------------------
// smem layout (floats):
#define OFF_X   0                        // sX [512][32]
#define OFF_H   (512*32)                 // sH [512][32]
#define OFF_WX  (2*512*32)               // sWx[512][16]
#define OFF_WH  (2*512*32 + 512*16)      // sWh[512][16]
#define OFF_RED (2*512*32 + 2*512*16)    // sRed[256][20]
#define SMEM_FLOATS (OFF_RED + 256*20)

__device__ __forceinline__ float sigf(float x)     { return 1.f / (1.f + __expf(-x)); }
__device__ __forceinline__ float tanh_fast(float x){ return 2.f / (1.f + __expf(-2.f * x)) - 1.f; }

#define FMA16(acc, hv, wv)                                               \
    acc[0][0] += hv.x * wv.x; acc[0][1] += hv.x * wv.y;                  \
    acc[0][2] += hv.x * wv.z; acc[0][3] += hv.x * wv.w;                  \
    acc[1][0] += hv.y * wv.x; acc[1][1] += hv.y * wv.y;                  \
    acc[1][2] += hv.y * wv.z; acc[1][3] += hv.y * wv.w;                  \
    acc[2][0] += hv.z * wv.x; acc[2][1] += hv.z * wv.y;                  \
    acc[2][2] += hv.z * wv.z; acc[2][3] += hv.z * wv.w;                  \
    acc[3][0] += hv.w * wv.x; acc[3][1] += hv.w * wv.y;                  \
    acc[3][2] += hv.w * wv.z; acc[3][3] += hv.w * wv.w;

__global__ __launch_bounds__(NTHR, 1)
void lstm_kernel(const float* __restrict__ x,
                 const float* __restrict__ h0, const float* __restrict__ c0,
                 const float* __restrict__ ww, const float* __restrict__ wb,
                 const float* __restrict__ mw, const float* __restrict__ mb,
                 float* __restrict__ out)
{
    extern __shared__ float smem[];
    float* sX   = smem + OFF_X;     // sX[k*32 + b]
    float* sH   = smem + OFF_H;     // sH[k*32 + b]
    float* sWx  = smem + OFF_WX;    // sWx[k*16 + j]
    float* sWh  = smem + OFF_WH;    // sWh[k*16 + j]
    float* sRed = smem + OFF_RED;   // sRed[tid*20 + v]

    const int tid = threadIdx.x;
    const int L0  = blockIdx.x * 4;

    // ---- load Wx (rows 0..511) and Wh (rows 512..1023) slices, 16 cols ----
    for (int it = tid; it < 16 * 512; it += NTHR) {
        int k = it >> 4;
        int j = it & 15;
        int g = j >> 2, jl = j & 3;
        float wx, wh;
        if (g < 3) {
            wx = ww[(size_t)k * GW + g * 512 + L0 + jl];
            wh = ww[(size_t)(512 + k) * GW + g * 512 + L0 + jl];
        } else {
            wx = mw[(size_t)k * L_ + L0 + jl];
            wh = mw[(size_t)(512 + k) * L_ + L0 + jl];
        }
        sWx[k * 16 + j] = wx;
        sWh[k * 16 + j] = wh;
    }

    // dot-product mapping: 8-way K split (warp = K chunk), 4x4 register block
    const int s  = tid >> 5;            // K chunk 0..7 (k in [s*64, s*64+64))
    const int u  = tid & 31;
    const int b0 = (u >> 2) * 4;        // batch block
    const int j0 = (u & 3) * 4;         // column block (gate g = u&3)
    const int kbase = s * 64;

    // epilogue mapping (tid < 128): one (b, l) pair per thread
    const int eb  = tid >> 2;
    const int ejl = tid & 3;
    float c_reg = 0.f;
    float bz[4];
    if (tid < 128) {
        c_reg = c0[eb * L_ + L0 + ejl];
        bz[0] = wb[0 * 512 + L0 + ejl];
        bz[1] = wb[1 * 512 + L0 + ejl];
        bz[2] = wb[2 * 512 + L0 + ejl];
        bz[3] = mb[L0 + ejl];
        // publish this CTA's slice of h0 into buffer 0
        g_hbuf[(L0 + ejl) * 32 + eb] = h0[eb * L_ + L0 + ejl];
        __threadfence();
    }
    __syncthreads();            // h0 slice + weights staged
    if (tid == 0) st_rel(&g_flags[blockIdx.x * 8], 1u);

    float* hid  = out;
    float* cell = out + (size_t)B_ * T_ * L_;

    // poll target for this warp's 16 producers
    const unsigned* myflag = &g_flags[(s * 16 + (u & 15)) * 8];
    // lane-b x stream: lane u reads batch u's k-chunk
    const float* xrow = x + (size_t)u * T_ * D_ + kbase;

    for (int t = 0; t < T_; t++) {
        // ---- stage x_t chunk (warp-local, no dependency) ----
        {
            const float* xg = xrow + (size_t)t * D_;
            #pragma unroll
            for (int q = 0; q < 16; q++) {
                float4 v = *(const float4*)(xg + q * 4);
                int kr = kbase + q * 4;
                sX[(kr + 0) * 32 + u] = v.x;
                sX[(kr + 1) * 32 + u] = v.y;
                sX[(kr + 2) * 32 + u] = v.z;
                sX[(kr + 3) * 32 + u] = v.w;
            }
            __syncwarp();
        }

        float acc[4][4];
        #pragma unroll
        for (int i = 0; i < 4; i++)
            #pragma unroll
            for (int j = 0; j < 4; j++) acc[i][j] = 0.f;

        // ---- x-part GEMM (overlaps producer latency) ----
        {
            const float* hp = sX  + kbase * 32 + b0;
            const float* wp = sWx + kbase * 16 + j0;
            #pragma unroll 8
            for (int kk = 0; kk < 64; kk++) {
                float4 hv = *(const float4*)hp;
                float4 wv = *(const float4*)wp;
                FMA16(acc, hv, wv)
                hp += 32; wp += 16;
            }
        }

        // ---- wait for my 16 producers, stage h block (warp-local) ----
        {
            const unsigned tgt = (unsigned)(t + 1);
            for (;;) {
                unsigned v = ld_acq(myflag);
                if (__all_sync(0xffffffffu, v >= tgt)) break;
            }
            const float* buf = g_hbuf + (size_t)(t & 1) * (L_ * 32);
            #pragma unroll
            for (int q = 0; q < 16; q++) {
                int f = q * 32 + u;
                int krow = kbase + (f >> 3);
                int c4 = (f & 7) * 4;
                float4 v4 = *(const float4*)&buf[krow * 32 + c4];
                *(float4*)&sH[krow * 32 + c4] = v4;
            }
            __syncwarp();
        }

        // ---- h-part GEMM (accumulate into same registers) ----
        {
            const float* hp = sH  + kbase * 32 + b0;
            const float* wp = sWh + kbase * 16 + j0;
            #pragma unroll 8
            for (int kk = 0; kk < 64; kk++) {
                float4 hv = *(const float4*)hp;
                float4 wv = *(const float4*)wp;
                FMA16(acc, hv, wv)
                hp += 32; wp += 16;
            }
        }

        #pragma unroll
        for (int i = 0; i < 4; i++) {
            float4 v = make_float4(acc[i][0], acc[i][1], acc[i][2], acc[i][3]);
            *(float4*)&sRed[tid * 20 + i * 4] = v;
        }
        __syncthreads();    // all chunks' partials in sRed

        // ---- reduce K chunks + gate epilogue + publish h(t+1) ----
        if (tid < 128) {
            float z[4];
            #pragma unroll
            for (int g = 0; g < 4; g++) {
                float v = 0.f;
                #pragma unroll
                for (int ss = 0; ss < 8; ss++)
                    v += sRed[(ss * 32 + (eb >> 2) * 4 + g) * 20 + (eb & 3) * 4 + ejl];
                z[g] = v + bz[g];
            }
            float ig = sigf(z[0]);
            float fg = sigf(z[1]);
            float og = sigf(z[2]);
            float mg = tanh_fast(z[3]);
            c_reg = fg * c_reg + ig * mg;
            float hn = og * tanh_fast(c_reg);
            size_t off = ((size_t)eb * T_ + t) * L_ + L0 + ejl;
            hid[off]  = hn;
            cell[off] = c_reg;
            if (t + 1 < T_) {
                // publish h(t+1) to the other parity buffer
                float* nb = g_hbuf + (size_t)((t + 1) & 1) * (L_ * 32);
                nb[(L0 + ejl) * 32 + eb] = hn;
                __threadfence();
            }
        }
        __syncthreads();    // sRed reads done (WAR) + h(t+1) stores fenced
        if (t + 1 < T_ && tid == 0)
            st_rel(&g_flags[blockIdx.x * 8], (unsigned)(t + 2));
    }
}

// ---------------------------------------------------------------------------
extern "C" void kernel_launch(void* const* d_in, const int* in_sizes, int n_in,
                              void* d_out, int out_size)
{
    const float* x  = (const float*)d_in[0];
    const float* h0 = (const float*)d_in[1];
    const float* c0 = (const float*)d_in[2];
    const float* ww = (const float*)d_in[3];
    const float* wb = (const float*)d_in[4];
    const float* mw = (const float*)d_in[5];
    const float* mb = (const float*)d_in[6];
    float* out = (float*)d_out;

    cudaFuncSetAttribute(lstm_kernel,
                         cudaFuncAttributeMaxDynamicSharedMemorySize,
                         SMEM_FLOATS * (int)sizeof(float));

    init_kernel<<<1, 256>>>();
    lstm_kernel<<<NCTA, NTHR, SMEM_FLOATS * (int)sizeof(float)>>>(
        x, h0, c0, ww, wb, mw, mb, out);
}

// round 10
// speedup vs baseline: 1.3812x; 1.3812x over previous
#include <cuda_runtime.h>
#include <cstdint>
#include <cstddef>

#define B_  32
#define T_  2048
#define D_  512
#define L_  512
#define NG  2048          // 3L gate cols + L candidate cols
#define GW  1536          // w_w column count

// 536 MB scratch for precomputed x-part of preactivations (+bias folded in).
// Layout: g_pre[(b*T + t)*NG + col]
__device__ float g_pre[(size_t)B_ * T_ * NG];

#define NCTA 128
// Per-CTA publication counters, 32B stride (one L2 sector each). No atomics.
__device__ unsigned int g_flags[NCTA * 8];
// Double-buffered h broadcast: g_hbuf[parity][l*32 + b]
__device__ float g_hbuf[2 * L_ * B_];

__device__ __forceinline__ unsigned ld_acq(const unsigned* p) {
    unsigned v;
    asm volatile("ld.acquire.gpu.global.u32 %0, [%1];" : "=r"(v) : "l"(p));
    return v;
}
__device__ __forceinline__ void st_rel(unsigned* p, unsigned v) {
    asm volatile("st.release.gpu.global.u32 [%0], %1;" :: "l"(p), "r"(v));
}

// ---------------------------------------------------------------------------
// Phase 1: PRE = X @ W_x + bias     (X: [65536, 512], W_x: [512, 2048])
// 128x128 tile, 8x8 microtile, 2 CTAs/SM. Double-buffered smem + register
// prefetch: one bar per k-tile, next tile's LDG overlaps current compute.
// Also resets the step flags (stream-ordered before lstm_kernel).
// ---------------------------------------------------------------------------
__global__ __launch_bounds__(256, 2)
void gemm_pre_kernel(const float* __restrict__ X,
                     const float* __restrict__ ww, const float* __restrict__ wb,
                     const float* __restrict__ mw, const float* __restrict__ mb)
{
    __shared__ float As[2][16][132];   // A tile, transposed: As[k][m]
    __shared__ float Bs[2][16][136];   // B tile: Bs[k][n]

    const int tid = threadIdx.x;
    if (blockIdx.x == 0 && blockIdx.y == 0) {
        #pragma unroll
        for (int r = 0; r < 4; r++) g_flags[r * 256 + tid] = 0u;
    }

    const int n0 = blockIdx.x * 128;
    const int m0 = blockIdx.y * 128;
    const int tx = tid & 15;        // n direction (16 * 8 = 128)
    const int ty = tid >> 4;        // m direction (16 * 8 = 128)

    const float* Bp; int ldb; const float* bias;
    if (n0 < GW) { Bp = ww + n0;        ldb = GW; bias = wb + n0; }
    else         { Bp = mw + (n0 - GW); ldb = L_; bias = mb + (n0 - GW); }

    float acc[8][8];
    #pragma unroll
    for (int i = 0; i < 8; i++)
        #pragma unroll
        for (int j = 0; j < 8; j++) acc[i][j] = 0.f;

    const int arow = tid >> 1;          // 0..127
    const int ak   = (tid & 1) * 8;     // 0 or 8
    const int brow = tid >> 4;          // 0..15
    const int bc   = (tid & 15) * 8;    // 0..120

    const float* Arow = X + (size_t)(m0 + arow) * D_ + ak;

    float ar[8], br[8];
    {   // preload tile k0 = 0
        *(float4*)(ar)     = *(const float4*)(Arow);
        *(float4*)(ar + 4) = *(const float4*)(Arow + 4);
        *(float4*)(br)     = *(const float4*)&Bp[(size_t)brow * ldb + bc];
        *(float4*)(br + 4) = *(const float4*)&Bp[(size_t)brow * ldb + bc + 4];
    }

    int buf = 0;
    for (int k0 = 0; k0 < D_; k0 += 16) {
        // stage current tile
        #pragma unroll
        for (int q = 0; q < 8; q++) As[buf][ak + q][arow] = ar[q];
        *(float4*)&Bs[buf][brow][bc]     = *(float4*)(br);
        *(float4*)&Bs[buf][brow][bc + 4] = *(float4*)(br + 4);
        __syncthreads();

        // prefetch next tile into registers (overlaps compute below)
        if (k0 + 16 < D_) {
            *(float4*)(ar)     = *(const float4*)(Arow + k0 + 16);
            *(float4*)(ar + 4) = *(const float4*)(Arow + k0 + 20);
            *(float4*)(br)     = *(const float4*)&Bp[(size_t)(k0 + 16 + brow) * ldb + bc];
            *(float4*)(br + 4) = *(const float4*)&Bp[(size_t)(k0 + 16 + brow) * ldb + bc + 4];
        }

        #pragma unroll
        for (int kk = 0; kk < 16; kk++) {
            float a[8], b[8];
            *(float4*)(a)     = *(const float4*)&As[buf][kk][ty * 8];
            *(float4*)(a + 4) = *(const float4*)&As[buf][kk][ty * 8 + 4];
            *(float4*)(b)     = *(const float4*)&Bs[buf][kk][tx * 8];
            *(float4*)(b + 4) = *(const float4*)&Bs[buf][kk][tx * 8 + 4];
            #pragma unroll
            for (int i = 0; i < 8; i++)
                #pragma unroll
                for (int j = 0; j < 8; j++)
                    acc[i][j] += a[i] * b[j];
        }
        buf ^= 1;
    }

    float bj[8];
    *(float4*)(bj)     = *(const float4*)&bias[tx * 8];
    *(float4*)(bj + 4) = *(const float4*)&bias[tx * 8 + 4];
    #pragma unroll
    for (int i = 0; i < 8; i++) {
        int r = m0 + ty * 8 + i;
        float4 o0, o1;
        o0.x = acc[i][0] + bj[0]; o0.y = acc[i][1] + bj[1];
        o0.z = acc[i][2] + bj[2]; o0.w = acc[i][3] + bj[3];
        o1.x = acc[i][4] + bj[4]; o1.y = acc[i][5] + bj[5];
        o1.z = acc[i][6] + bj[6]; o1.w = acc[i][7] + bj[7];
        *(float4*)&g_pre[(size_t)r * NG + n0 + tx * 8]     = o0;
        *(float4*)&g_pre[(size_t)r * NG + n0 + tx * 8 + 4] = o1;
    }
}

// ---------------------------------------------------------------------------
// Phase 2: persistent recurrent kernel, decentralized pipelined handoff.
// 128 CTAs, CTA i owns l in [4i, 4i+4) => 16 gate columns.
// h(t) published per-CTA to double-buffered g_hbuf + per-CTA flag (=t+1).
// Warp s (k-chunk [64s,64s+64)) polls only its 16 producer flags and copies
// its 8KB h block to smem. Epilogue on warps 0-3 only; sRed double-buffered
// so warps 4-7 overlap next-step staging with the epilogue; flag released
// after a 128-thread named barrier (release chain via bar transitivity —
// no MEMBAR.GPU needed). Flags reset by gemm_pre_kernel each launch.
// ---------------------------------------------------------------------------
#define NTHR 256
// smem: sH[512][36] + sW[512][20] + sRed[2][256][20]
#define SMEM_FLOATS (512*36 + 512*20 + 2*256*20)

__device__ __forceinline__ float sigf(float x)     { return 1.f / (1.f + __expf(-x)); }
__device__ __forceinline__ float tanh_fast(float x){ return 2.f / (1.f + __expf(-2.f * x)) - 1.f; }

__global__ __launch_bounds__(NTHR, 1)
void lstm_kernel(const float* __restrict__ h0, const float* __restrict__ c0,
                 const float* __restrict__ ww, const float* __restrict__ mw,
                 float* __restrict__ out)
{
    extern __shared__ float smem[];
    float* sH   = smem;                 // sH[k*36 + b]
    float* sW   = smem + 512 * 36;      // sW[k*20 + j]
    float* sRed = sW + 512 * 20;        // sRed[par][tid*20 + v]

    const int tid = threadIdx.x;
    const int L0  = blockIdx.x * 4;

    // ---- load W_h slice once: col(j) = (j>>2)*512 + L0 + (j&3), rows 512+k ----
    for (int it = tid; it < 16 * 512; it += NTHR) {
        int k = it >> 4;
        int j = it & 15;
        int g = j >> 2, jl = j & 3;
        float w;
        if (g < 3) w = ww[(size_t)(512 + k) * GW + g * 512 + L0 + jl];
        else       w = mw[(size_t)(512 + k) * L_ + L0 + jl];
        sW[k * 20 + j] = w;
    }

    // dot-product mapping: 8-way K split (warp = K chunk), 4x4 register block
    const int s  = tid >> 5;            // K chunk 0..7 (k in [s*64, s*64+64))
    const int u  = tid & 31;
    const int b0 = (u >> 2) * 4;        // batch block
    const int j0 = (u & 3) * 4;         // column block
    const int kbase = s * 64;

    // epilogue mapping (tid < 128): one (b, l) pair per thread
    const int eb  = tid >> 2;
    const int ejl = tid & 3;
    float c_reg = 0.f;
    float pre_r[4];
    if (tid < 128) {
        c_reg = c0[eb * L_ + L0 + ejl];
        #pragma unroll
        for (int g = 0; g < 4; g++)
            pre_r[g] = g_pre[(size_t)eb * T_ * NG + g * 512 + L0 + ejl];
        // publish this CTA's slice of h0 into buffer 0
        g_hbuf[(L0 + ejl) * 32 + eb] = h0[eb * L_ + L0 + ejl];
    }
    __syncthreads();            // h0 slice + sW staged (release via bar + st_rel)
    if (tid == 0) st_rel(&g_flags[blockIdx.x * 8], 1u);

    float* hid  = out;
    float* cell = out + (size_t)B_ * T_ * L_;

    // poll target for this warp's 16 producers
    const unsigned* myflag = &g_flags[(s * 16 + (u & 15)) * 8];

    int par = 0;
    for (int t = 0; t < T_; t++) {
        // ---- per-warp: wait for my 16 producers, stage my 8KB h block ----
        {
            const unsigned tgt = (unsigned)(t + 1);
            for (;;) {
                unsigned v = ld_acq(myflag);
                if (__all_sync(0xffffffffu, v >= tgt)) break;
            }
            const float* buf = g_hbuf + (size_t)(t & 1) * (L_ * 32);
            #pragma unroll
            for (int q = 0; q < 16; q++) {
                int f = q * 32 + u;
                int krow = kbase + (f >> 3);
                int c4 = (f & 7) * 4;
                float4 v4 = *(const float4*)&buf[krow * 32 + c4];
                *(float4*)&sH[krow * 36 + c4] = v4;
            }
            __syncwarp();
        }

        // ---- h-part dot product (warp-local data) ----
        float acc[4][4];
        #pragma unroll
        for (int i = 0; i < 4; i++)
            #pragma unroll
            for (int j = 0; j < 4; j++) acc[i][j] = 0.f;

        const float* hp = sH + kbase * 36 + b0;
        const float* wp = sW + kbase * 20 + j0;
        #pragma unroll 8
        for (int kk = 0; kk < 64; kk++) {
            float4 hv = *(const float4*)hp;
            float4 wv = *(const float4*)wp;
            acc[0][0] += hv.x * wv.x; acc[0][1] += hv.x * wv.y;
            acc[0][2] += hv.x * wv.z; acc[0][3] += hv.x * wv.w;
            acc[1][0] += hv.y * wv.x; acc[1][1] += hv.y * wv.y;
            acc[1][2] += hv.y * wv.z; acc[1][3] += hv.y * wv.w;
            acc[2][0] += hv.z * wv.x; acc[2][1] += hv.z * wv.y;
            acc[2][2] += hv.z * wv.z; acc[2][3] += hv.z * wv.w;
            acc[3][0] += hv.w * wv.x; acc[3][1] += hv.w * wv.y;
            acc[3][2] += hv.w * wv.z; acc[3][3] += hv.w * wv.w;
            hp += 36; wp += 20;
        }
        float* red = sRed + par * (256 * 20);
        #pragma unroll
        for (int i = 0; i < 4; i++) {
            float4 v = make_float4(acc[i][0], acc[i][1], acc[i][2], acc[i][3]);
            *(float4*)&red[tid * 20 + i * 4] = v;
        }
        __syncthreads();    // all partials in sRed[par]; warps 4-7 run ahead after this

        // ---- reduce K chunks + gate epilogue + publish h(t+1) (warps 0-3) ----
        if (tid < 128) {
            float z[4];
            #pragma unroll
            for (int g = 0; g < 4; g++) {
                float v = 0.f;
                #pragma unroll
                for (int ss = 0; ss < 8; ss++)
                    v += red[(ss * 32 + (eb >> 2) * 4 + g) * 20 + (eb & 3) * 4 + ejl];
                z[g] = v + pre_r[g];
            }
            float ig = sigf(z[0]);
            float fg = sigf(z[1]);
            float og = sigf(z[2]);
            float mg = tanh_fast(z[3]);
            c_reg = fg * c_reg + ig * mg;
            float hn = og * tanh_fast(c_reg);
            size_t off = ((size_t)eb * T_ + t) * L_ + L0 + ejl;
            hid[off]  = hn;
            cell[off] = c_reg;
            if (t + 1 < T_) {
                // publish h(t+1) to the other parity buffer
                float* nb = g_hbuf + (size_t)((t + 1) & 1) * (L_ * 32);
                nb[(L0 + ejl) * 32 + eb] = hn;
                // prefetch next step's x-part (latency hides under next GEMM)
                #pragma unroll
                for (int g = 0; g < 4; g++)
                    pre_r[g] = g_pre[((size_t)eb * T_ + (t + 1)) * NG + g * 512 + L0 + ejl];
                // 128-thread named barrier: all epilogue h-stores done, then
                // one release-store of the flag (hb transitive through bar).
                asm volatile("bar.sync 1, 128;" ::: "memory");
                if (tid == 0)
                    st_rel(&g_flags[blockIdx.x * 8], (unsigned)(t + 2));
            }
        }
        par ^= 1;
    }
}

// ---------------------------------------------------------------------------
extern "C" void kernel_launch(void* const* d_in, const int* in_sizes, int n_in,
                              void* d_out, int out_size)
{
    const float* x  = (const float*)d_in[0];
    const float* h0 = (const float*)d_in[1];
    const float* c0 = (const float*)d_in[2];
    const float* ww = (const float*)d_in[3];
    const float* wb = (const float*)d_in[4];
    const float* mw = (const float*)d_in[5];
    const float* mb = (const float*)d_in[6];
    float* out = (float*)d_out;

    cudaFuncSetAttribute(lstm_kernel,
                         cudaFuncAttributeMaxDynamicSharedMemorySize,
                         SMEM_FLOATS * (int)sizeof(float));

    gemm_pre_kernel<<<dim3(NG / 128, (B_ * T_) / 128), 256>>>(x, ww, wb, mw, mb);
    lstm_kernel<<<NCTA, NTHR, SMEM_FLOATS * (int)sizeof(float)>>>(h0, c0, ww, mw, out);
}

// round 12
// speedup vs baseline: 1.4077x; 1.0192x over previous
#include <cuda_runtime.h>
#include <cuda_bf16.h>
#include <cstdint>
#include <cstddef>

#define B_  32
#define T_  2048
#define D_  512
#define L_  512
#define NG  2048          // 3L gate cols + L candidate cols
#define GW  1536          // w_w column count

// Scratch: precomputed x-part of preactivations (+bias), and bf16 split copies.
__device__ float g_pre[(size_t)B_ * T_ * NG];
__device__ __nv_bfloat16 g_xhi[(size_t)B_ * T_ * D_];
__device__ __nv_bfloat16 g_xlo[(size_t)B_ * T_ * D_];
__device__ __nv_bfloat16 g_whi[(size_t)NG * D_];   // W^T [n][k], ww+mw merged
__device__ __nv_bfloat16 g_wlo[(size_t)NG * D_];

#define NCTA 128
// Per-CTA publication counters, 32B stride (one L2 sector each). No atomics.
__device__ unsigned int g_flags[NCTA * 8];
// Double-buffered h broadcast: g_hbuf[parity][l*32 + b]
__device__ float g_hbuf[2 * L_ * B_];

__device__ __forceinline__ unsigned ld_acq(const unsigned* p) {
    unsigned v;
    asm volatile("ld.acquire.gpu.global.u32 %0, [%1];" : "=r"(v) : "l"(p));
    return v;
}
__device__ __forceinline__ void st_rel(unsigned* p, unsigned v) {
    asm volatile("st.release.gpu.global.u32 [%0], %1;" :: "l"(p), "r"(v));
}

// ---------------------------------------------------------------------------
// Prep kernels: split fp32 -> bf16 hi/lo
// ---------------------------------------------------------------------------
__global__ __launch_bounds__(256)
void convx_kernel(const float* __restrict__ x)
{
    size_t i = ((size_t)blockIdx.x * 256 + threadIdx.x) * 4;
    float4 v = *(const float4*)(x + i);
    __nv_bfloat16 h0 = __float2bfloat16(v.x);
    __nv_bfloat16 h1 = __float2bfloat16(v.y);
    __nv_bfloat16 h2 = __float2bfloat16(v.z);
    __nv_bfloat16 h3 = __float2bfloat16(v.w);
    ushort4 hs, ls;
    hs.x = __bfloat16_as_ushort(h0); hs.y = __bfloat16_as_ushort(h1);
    hs.z = __bfloat16_as_ushort(h2); hs.w = __bfloat16_as_ushort(h3);
    ls.x = __bfloat16_as_ushort(__float2bfloat16(v.x - __bfloat162float(h0)));
    ls.y = __bfloat16_as_ushort(__float2bfloat16(v.y - __bfloat162float(h1)));
    ls.z = __bfloat16_as_ushort(__float2bfloat16(v.z - __bfloat162float(h2)));
    ls.w = __bfloat16_as_ushort(__float2bfloat16(v.w - __bfloat162float(h3)));
    *(ushort4*)&g_xhi[i] = hs;
    *(ushort4*)&g_xlo[i] = ls;
}

__global__ __launch_bounds__(256)
void convw_kernel(const float* __restrict__ ww, const float* __restrict__ mw)
{
    const int tid = threadIdx.x;
    if (blockIdx.x == 0) {
        #pragma unroll
        for (int r = 0; r < 4; r++) g_flags[r * 256 + tid] = 0u;
    }
    int i = blockIdx.x * 256 + tid;        // 0 .. NG*512-1
    int n = i >> 9;
    int k = i & 511;
    float w = (n < GW) ? ww[(size_t)k * GW + n] : mw[(size_t)k * L_ + (n - GW)];
    __nv_bfloat16 h = __float2bfloat16(w);
    g_whi[(size_t)n * 512 + k] = h;
    g_wlo[(size_t)n * 512 + k] = __float2bfloat16(w - __bfloat162float(h));
}

// ---------------------------------------------------------------------------
// Phase 1 (tensor, mma.sync): PRE = X @ W_x + bias via bf16x3 split HMMA.
// 128x128 CTA tile, 8 warps (2x4) -> 64x32 per warp, K in 4 chunks of 128.
// A[m][k] and B(=W^T)[n][k] in smem with 136-elem row pad: every fragment
// register is a contiguous bf16x2 -> direct conflict-free LDS.32 (no ldmatrix).
// ---------------------------------------------------------------------------
#define AHI_OFF 0
#define ALO_OFF (128*136)
#define BHI_OFF (2*128*136)
#define BLO_OFF (3*128*136)
#define BIAS_BYTES_OFF (4*128*136*2)
#define GS_TOTAL (BIAS_BYTES_OFF + 512)

__device__ __forceinline__ void mma16816(float* d, const uint32_t* a, const uint32_t* b) {
    asm volatile(
        "mma.sync.aligned.m16n8k16.row.col.f32.bf16.bf16.f32 "
        "{%0,%1,%2,%3}, {%4,%5,%6,%7}, {%8,%9}, {%0,%1,%2,%3};"
        : "+f"(d[0]), "+f"(d[1]), "+f"(d[2]), "+f"(d[3])
        : "r"(a[0]), "r"(a[1]), "r"(a[2]), "r"(a[3]), "r"(b[0]), "r"(b[1]));
}

__global__ __launch_bounds__(256, 1)
void gemm_mma_kernel(const float* __restrict__ wb, const float* __restrict__ mb)
{
    extern __shared__ char sm[];
    __nv_bfloat16* sAhi = (__nv_bfloat16*)sm + AHI_OFF;
    __nv_bfloat16* sAlo = (__nv_bfloat16*)sm + ALO_OFF;
    __nv_bfloat16* sBhi = (__nv_bfloat16*)sm + BHI_OFF;
    __nv_bfloat16* sBlo = (__nv_bfloat16*)sm + BLO_OFF;
    float* sBias = (float*)(sm + BIAS_BYTES_OFF);

    const int tid  = threadIdx.x;
    const int wid  = tid >> 5;
    const int lane = tid & 31;
    const int mh   = wid >> 2;          // warp M half (0-1) -> 64 rows
    const int nq   = wid & 3;           // warp N quarter (0-3) -> 32 cols
    const int l4   = lane >> 2;         // 0..7
    const int l2   = (lane & 3) * 2;    // 0,2,4,6
    const int n0 = blockIdx.x * 128;
    const int m0 = blockIdx.y * 128;

    if (tid < 128)
        sBias[tid] = (n0 + tid < GW) ? wb[n0 + tid] : mb[n0 + tid - GW];

    float acc[4][4][4];                 // [mt][nt][reg]
    #pragma unroll
    for (int mt = 0; mt < 4; mt++)
        #pragma unroll
        for (int nt = 0; nt < 4; nt++)
            #pragma unroll
            for (int r = 0; r < 4; r++) acc[mt][nt][r] = 0.f;

    const int srow = tid >> 1;            // staging row 0..127
    const int skb  = (tid & 1) * 8;       // uint4 index within row: 8 per half

    for (int c = 0; c < 4; c++) {
        // ---- stage hi/lo A and B chunks: 128 rows x 128 k bf16 each ----
        #pragma unroll
        for (int h = 0; h < 8; h++) {
            int kb = skb + h;                      // 0..15 (16B units)
            size_t ga = (size_t)(m0 + srow) * 512 + c * 128 + kb * 8;
            size_t gb = (size_t)(n0 + srow) * 512 + c * 128 + kb * 8;
            uint32_t so = srow * 136 + kb * 8;
            *(uint4*)&sAhi[so] = *(const uint4*)&g_xhi[ga];
            *(uint4*)&sAlo[so] = *(const uint4*)&g_xlo[ga];
            *(uint4*)&sBhi[so] = *(const uint4*)&g_whi[gb];
            *(uint4*)&sBlo[so] = *(const uint4*)&g_wlo[gb];
        }
        __syncthreads();

        #pragma unroll
        for (int p = 0; p < 3; p++) {
            const __nv_bfloat16* Ab = (p == 2) ? sAlo : sAhi;
            const __nv_bfloat16* Bb = (p == 1) ? sBlo : sBhi;
            #pragma unroll
            for (int ks = 0; ks < 8; ks++) {
                const int C = ks * 16;
                uint32_t bf[4][2];
                #pragma unroll
                for (int nt = 0; nt < 4; nt++) {
                    int nr = nq * 32 + nt * 8 + l4;
                    bf[nt][0] = *(const uint32_t*)&Bb[nr * 136 + C + l2];
                    bf[nt][1] = *(const uint32_t*)&Bb[nr * 136 + C + 8 + l2];
                }
                #pragma unroll
                for (int mt = 0; mt < 4; mt++) {
                    int r = mh * 64 + mt * 16 + l4;
                    uint32_t af[4];
                    af[0] = *(const uint32_t*)&Ab[r * 136 + C + l2];
                    af[1] = *(const uint32_t*)&Ab[(r + 8) * 136 + C + l2];
                    af[2] = *(const uint32_t*)&Ab[r * 136 + C + 8 + l2];
                    af[3] = *(const uint32_t*)&Ab[(r + 8) * 136 + C + 8 + l2];
                    #pragma unroll
                    for (int nt = 0; nt < 4; nt++)
                        mma16816(acc[mt][nt], af, bf[nt]);
                }
            }
        }
        __syncthreads();
    }

    // ---- epilogue: registers + bias -> gmem (float2 per fragment row) ----
    #pragma unroll
    for (int mt = 0; mt < 4; mt++) {
        int gr = m0 + mh * 64 + mt * 16 + l4;
        #pragma unroll
        for (int nt = 0; nt < 4; nt++) {
            int lc = nq * 32 + nt * 8 + l2;
            float b0 = sBias[lc], b1 = sBias[lc + 1];
            float2 o0 = make_float2(acc[mt][nt][0] + b0, acc[mt][nt][1] + b1);
            float2 o1 = make_float2(acc[mt][nt][2] + b0, acc[mt][nt][3] + b1);
            *(float2*)&g_pre[(size_t)gr * NG + n0 + lc]       = o0;
            *(float2*)&g_pre[(size_t)(gr + 8) * NG + n0 + lc] = o1;
        }
    }
}

// ---------------------------------------------------------------------------
// Phase 2: persistent recurrent kernel (UNCHANGED from round 10).
// ---------------------------------------------------------------------------
#define NTHR 256
#define SMEM_FLOATS (512*36 + 512*20 + 2*256*20)

__device__ __forceinline__ float sigf(float x)     { return 1.f / (1.f + __expf(-x)); }
__device__ __forceinline__ float tanh_fast(float x){ return 2.f / (1.f + __expf(-2.f * x)) - 1.f; }

__global__ __launch_bounds__(NTHR, 1)
void lstm_kernel(const float* __restrict__ h0, const float* __restrict__ c0,
                 const float* __restrict__ ww, const float* __restrict__ mw,
                 float* __restrict__ out)
{
    extern __shared__ float smem[];
    float* sH   = smem;                 // sH[k*36 + b]
    float* sW   = smem + 512 * 36;      // sW[k*20 + j]
    float* sRed = sW + 512 * 20;        // sRed[par][tid*20 + v]

    const int tid = threadIdx.x;
    const int L0  = blockIdx.x * 4;

    for (int it = tid; it < 16 * 512; it += NTHR) {
        int k = it >> 4;
        int j = it & 15;
        int g = j >> 2, jl = j & 3;
        float w;
        if (g < 3) w = ww[(size_t)(512 + k) * GW + g * 512 + L0 + jl];
        else       w = mw[(size_t)(512 + k) * L_ + L0 + jl];
        sW[k * 20 + j] = w;
    }

    const int s  = tid >> 5;
    const int u  = tid & 31;
    const int b0 = (u >> 2) * 4;
    const int j0 = (u & 3) * 4;
    const int kbase = s * 64;

    const int eb  = tid >> 2;
    const int ejl = tid & 3;
    float c_reg = 0.f;
    float pre_r[4];
    if (tid < 128) {
        c_reg = c0[eb * L_ + L0 + ejl];
        #pragma unroll
        for (int g = 0; g < 4; g++)
            pre_r[g] = g_pre[(size_t)eb * T_ * NG + g * 512 + L0 + ejl];
        g_hbuf[(L0 + ejl) * 32 + eb] = h0[eb * L_ + L0 + ejl];
    }
    __syncthreads();
    if (tid == 0) st_rel(&g_flags[blockIdx.x * 8], 1u);

    float* hid  = out;
    float* cell = out + (size_t)B_ * T_ * L_;

    const unsigned* myflag = &g_flags[(s * 16 + (u & 15)) * 8];

    int par = 0;
    for (int t = 0; t < T_; t++) {
        {
            const unsigned tgt = (unsigned)(t + 1);
            for (;;) {
                unsigned v = ld_acq(myflag);
                if (__all_sync(0xffffffffu, v >= tgt)) break;
            }
            const float* buf = g_hbuf + (size_t)(t & 1) * (L_ * 32);
            #pragma unroll
            for (int q = 0; q < 16; q++) {
                int f = q * 32 + u;
                int krow = kbase + (f >> 3);
                int c4 = (f & 7) * 4;
                float4 v4 = *(const float4*)&buf[krow * 32 + c4];
                *(float4*)&sH[krow * 36 + c4] = v4;
            }
            __syncwarp();
        }

        float acc[4][4];
        #pragma unroll
        for (int i = 0; i < 4; i++)
            #pragma unroll
            for (int j = 0; j < 4; j++) acc[i][j] = 0.f;

        const float* hp = sH + kbase * 36 + b0;
        const float* wp = sW + kbase * 20 + j0;
        #pragma unroll 8
        for (int kk = 0; kk < 64; kk++) {
            float4 hv = *(const float4*)hp;
            float4 wv = *(const float4*)wp;
            acc[0][0] += hv.x * wv.x; acc[0][1] += hv.x * wv.y;
            acc[0][2] += hv.x * wv.z; acc[0][3] += hv.x * wv.w;
            acc[1][0] += hv.y * wv.x; acc[1][1] += hv.y * wv.y;
            acc[1][2] += hv.y * wv.z; acc[1][3] += hv.y * wv.w;
            acc[2][0] += hv.z * wv.x; acc[2][1] += hv.z * wv.y;
            acc[2][2] += hv.z * wv.z; acc[2][3] += hv.z * wv.w;
            acc[3][0] += hv.w * wv.x; acc[3][1] += hv.w * wv.y;
            acc[3][2] += hv.w * wv.z; acc[3][3] += hv.w * wv.w;
            hp += 36; wp += 20;
        }
        float* red = sRed + par * (256 * 20);
        #pragma unroll
        for (int i = 0; i < 4; i++) {
            float4 v = make_float4(acc[i][0], acc[i][1], acc[i][2], acc[i][3]);
            *(float4*)&red[tid * 20 + i * 4] = v;
        }
        __syncthreads();

        if (tid < 128) {
            float z[4];
            #pragma unroll
            for (int g = 0; g < 4; g++) {
                float v = 0.f;
                #pragma unroll
                for (int ss = 0; ss < 8; ss++)
                    v += red[(ss * 32 + (eb >> 2) * 4 + g) * 20 + (eb & 3) * 4 + ejl];
                z[g] = v + pre_r[g];
            }
            float ig = sigf(z[0]);
            float fg = sigf(z[1]);
            float og = sigf(z[2]);
            float mg = tanh_fast(z[3]);
            c_reg = fg * c_reg + ig * mg;
            float hn = og * tanh_fast(c_reg);
            size_t off = ((size_t)eb * T_ + t) * L_ + L0 + ejl;
            hid[off]  = hn;
            cell[off] = c_reg;
            if (t + 1 < T_) {
                float* nb = g_hbuf + (size_t)((t + 1) & 1) * (L_ * 32);
                nb[(L0 + ejl) * 32 + eb] = hn;
                #pragma unroll
                for (int g = 0; g < 4; g++)
                    pre_r[g] = g_pre[((size_t)eb * T_ + (t + 1)) * NG + g * 512 + L0 + ejl];
                asm volatile("bar.sync 1, 128;" ::: "memory");
                if (tid == 0)
                    st_rel(&g_flags[blockIdx.x * 8], (unsigned)(t + 2));
            }
        }
        par ^= 1;
    }
}

// ---------------------------------------------------------------------------
extern "C" void kernel_launch(void* const* d_in, const int* in_sizes, int n_in,
                              void* d_out, int out_size)
{
    const float* x  = (const float*)d_in[0];
    const float* h0 = (const float*)d_in[1];
    const float* c0 = (const float*)d_in[2];
    const float* ww = (const float*)d_in[3];
    const float* wb = (const float*)d_in[4];
    const float* mw = (const float*)d_in[5];
    const float* mb = (const float*)d_in[6];
    float* out = (float*)d_out;

    cudaFuncSetAttribute(gemm_mma_kernel,
                         cudaFuncAttributeMaxDynamicSharedMemorySize, GS_TOTAL);
    cudaFuncSetAttribute(lstm_kernel,
                         cudaFuncAttributeMaxDynamicSharedMemorySize,
                         SMEM_FLOATS * (int)sizeof(float));

    convx_kernel<<<32768, 256>>>(x);
    convw_kernel<<<4096, 256>>>(ww, mw);
    gemm_mma_kernel<<<dim3(16, 512), 256, GS_TOTAL>>>(wb, mb);
    lstm_kernel<<<NCTA, NTHR, SMEM_FLOATS * (int)sizeof(float)>>>(h0, c0, ww, mw, out);
}